// round 1
// baseline (speedup 1.0000x reference)
#include <cuda_runtime.h>

// Problem constants (fixed by setup_inputs)
#define BB      2048   // batch
#define NPATCH  196    // patches
#define DD      1024   // dino dim
#define DC      512    // clip dim

// Scratch (allocation-free rule: __device__ globals)
__device__ float g_t[(size_t)BB * DD];     // projected+tanh+normalized text emb
__device__ float g_vsel[(size_t)BB * DD];  // selected+normalized visual emb

// ---------------------------------------------------------------------------
// GEMM: C[M,N] = A[M,K] * B[N,K]^T   (both row-major, K-major contraction)
// BM=BN=128, BK=16, 256 threads, 8x8 per-thread microtile.
// Optional epilogue: C = tanh(C + bias[n])
// N is derived as gridDim.x*128; M as gridDim.y*128. K multiple of 16.
// ---------------------------------------------------------------------------
template <bool TANH>
__global__ __launch_bounds__(256, 2)
void gemm_abt(const float* __restrict__ A, const float* __restrict__ Bm,
              const float* __restrict__ bias, float* __restrict__ C, int K)
{
    __shared__ float As[16][128];
    __shared__ float Bs[16][128];

    const int tid = threadIdx.x;
    const int bm  = blockIdx.y * 128;
    const int bn  = blockIdx.x * 128;
    const int N   = gridDim.x * 128;
    const int tx  = tid & 15;   // 0..15  -> 8 cols each
    const int ty  = tid >> 4;   // 0..15  -> 8 rows each

    // gmem tile load mapping: each thread loads 2 rows (lr, lr+64), 1 float4 each
    const int lr = tid >> 2;          // 0..63
    const int lc = (tid & 3) * 4;     // 0,4,8,12

    float acc[8][8];
#pragma unroll
    for (int i = 0; i < 8; i++)
#pragma unroll
        for (int j = 0; j < 8; j++) acc[i][j] = 0.f;

    const float* Aptr = A + (size_t)bm * K;
    const float* Bptr = Bm + (size_t)bn * K;

    for (int k0 = 0; k0 < K; k0 += 16) {
#pragma unroll
        for (int h = 0; h < 2; h++) {
            const int row = lr + h * 64;
            float4 a = *(const float4*)(Aptr + (size_t)row * K + k0 + lc);
            As[lc + 0][row] = a.x; As[lc + 1][row] = a.y;
            As[lc + 2][row] = a.z; As[lc + 3][row] = a.w;
            float4 b = *(const float4*)(Bptr + (size_t)row * K + k0 + lc);
            Bs[lc + 0][row] = b.x; Bs[lc + 1][row] = b.y;
            Bs[lc + 2][row] = b.z; Bs[lc + 3][row] = b.w;
        }
        __syncthreads();

#pragma unroll
        for (int k = 0; k < 16; k++) {
            float af[8], bf[8];
            *(float4*)&af[0] = *(const float4*)&As[k][ty * 8];
            *(float4*)&af[4] = *(const float4*)&As[k][ty * 8 + 4];
            *(float4*)&bf[0] = *(const float4*)&Bs[k][tx * 8];
            *(float4*)&bf[4] = *(const float4*)&Bs[k][tx * 8 + 4];
#pragma unroll
            for (int i = 0; i < 8; i++)
#pragma unroll
                for (int j = 0; j < 8; j++)
                    acc[i][j] = fmaf(af[i], bf[j], acc[i][j]);
        }
        __syncthreads();
    }

    // Epilogue
#pragma unroll
    for (int i = 0; i < 8; i++) {
        float* Crow = C + (size_t)(bm + ty * 8 + i) * N + bn + tx * 8;
        float v[8];
#pragma unroll
        for (int j = 0; j < 8; j++) {
            float x = acc[i][j];
            if (TANH) x = tanhf(x + bias[bn + tx * 8 + j]);
            v[j] = x;
        }
        *(float4*)(Crow + 0) = make_float4(v[0], v[1], v[2], v[3]);
        *(float4*)(Crow + 4) = make_float4(v[4], v[5], v[6], v[7]);
    }
}

// ---------------------------------------------------------------------------
// In-place row L2 normalization of X[rows, DD].  One block per row,
// 256 threads * float4 == 1024 elements. Matches F.normalize eps=1e-12
// (scale = rsqrt(max(sumsq, 1e-24)) == 1/max(norm, 1e-12) for sumsq>0).
// ---------------------------------------------------------------------------
__global__ __launch_bounds__(256)
void normalize_rows(float* __restrict__ X)
{
    const int row = blockIdx.x;
    const int tid = threadIdx.x;
    float4* p = (float4*)(X + (size_t)row * DD);
    float4 a = p[tid];
    float s = a.x * a.x + a.y * a.y + a.z * a.z + a.w * a.w;
#pragma unroll
    for (int o = 16; o; o >>= 1) s += __shfl_xor_sync(0xffffffffu, s, o);

    __shared__ float red[8];
    if ((tid & 31) == 0) red[tid >> 5] = s;
    __syncthreads();
    float tot = red[0] + red[1] + red[2] + red[3] +
                red[4] + red[5] + red[6] + red[7];
    float scale = rsqrtf(fmaxf(tot, 1e-24f));
    a.x *= scale; a.y *= scale; a.z *= scale; a.w *= scale;
    p[tid] = a;
}

// ---------------------------------------------------------------------------
// Per-batch: stream v[b, j, :] once; score_j = dot(t_b, v_bj) / ||v_bj||;
// argmax_j (== argmax of softmax); write v_sel[b] = v[b, jmax] / ||v[b,jmax]||.
// One block per batch element, 256 threads, float4 per thread per row.
// Software-pipelined: next row's load issued before this row's reduction.
// ---------------------------------------------------------------------------
__global__ __launch_bounds__(256)
void argmax_gather(const float* __restrict__ V)
{
    const int b   = blockIdx.x;
    const int tid = threadIdx.x;
    const int lane = tid & 31, warp = tid >> 5;

    const float4* tp = (const float4*)(g_t + (size_t)b * DD);
    const float4  tf = tp[tid];

    const float4* vp = (const float4*)(V + (size_t)b * NPATCH * DD);

    __shared__ float red_d[8];
    __shared__ float red_n[8];

    float best = -3.402823e38f;
    int   bj   = 0;
    float bnsq = 1.0f;

    float4 cur = vp[tid];  // j = 0
    for (int j = 0; j < NPATCH; j++) {
        float4 nxt = cur;
        if (j + 1 < NPATCH) nxt = vp[(size_t)(j + 1) * (DD / 4) + tid];

        float d = cur.x * tf.x + cur.y * tf.y + cur.z * tf.z + cur.w * tf.w;
        float n = cur.x * cur.x + cur.y * cur.y + cur.z * cur.z + cur.w * cur.w;
#pragma unroll
        for (int o = 16; o; o >>= 1) {
            d += __shfl_xor_sync(0xffffffffu, d, o);
            n += __shfl_xor_sync(0xffffffffu, n, o);
        }
        if (lane == 0) { red_d[warp] = d; red_n[warp] = n; }
        __syncthreads();
        // every thread computes the identical totals -> identical argmax state
        float td = red_d[0] + red_d[1] + red_d[2] + red_d[3] +
                   red_d[4] + red_d[5] + red_d[6] + red_d[7];
        float tn = red_n[0] + red_n[1] + red_n[2] + red_n[3] +
                   red_n[4] + red_n[5] + red_n[6] + red_n[7];
        float score = td * rsqrtf(fmaxf(tn, 1e-24f));
        if (score > best) { best = score; bj = j; bnsq = tn; }
        __syncthreads();  // protect smem reuse next iteration
        cur = nxt;
    }

    const float scale = rsqrtf(fmaxf(bnsq, 1e-24f));
    float4 s = vp[(size_t)bj * (DD / 4) + tid];
    s.x *= scale; s.y *= scale; s.z *= scale; s.w *= scale;
    ((float4*)(g_vsel + (size_t)b * DD))[tid] = s;
}

// ---------------------------------------------------------------------------
// Launch: inputs in metadata order:
//   d_in[0] visual_embedding [2048,196,1024] f32
//   d_in[1] textual_embedding [2048,512]     f32
//   d_in[2] W                 [1024,512]     f32
//   d_in[3] b                 [1024]         f32
// d_out: [2048,2048] f32
// ---------------------------------------------------------------------------
extern "C" void kernel_launch(void* const* d_in, const int* in_sizes, int n_in,
                              void* d_out, int out_size)
{
    const float* visual  = (const float*)d_in[0];
    const float* textual = (const float*)d_in[1];
    const float* W       = (const float*)d_in[2];
    const float* bias    = (const float*)d_in[3];
    float* out = (float*)d_out;

    float *t_ptr = nullptr, *vsel_ptr = nullptr;
    cudaGetSymbolAddress((void**)&t_ptr, g_t);
    cudaGetSymbolAddress((void**)&vsel_ptr, g_vsel);

    // 1) t_raw = tanh(textual @ W^T + b)   [2048,1024]
    gemm_abt<true><<<dim3(DD / 128, BB / 128), 256>>>(textual, W, bias, t_ptr, DC);
    // 2) t = l2norm(t_raw)
    normalize_rows<<<BB, 256>>>(t_ptr);
    // 3) argmax over patches + gather normalized selected visual embedding
    argmax_gather<<<BB, 256>>>(visual);
    // 4) out = t @ v_sel^T   [2048,2048]
    gemm_abt<false><<<dim3(BB / 128, BB / 128), 256>>>(t_ptr, vsel_ptr, nullptr, out, DD);
}

// round 2
// speedup vs baseline: 1.1673x; 1.1673x over previous
#include <cuda_runtime.h>

// Problem constants (fixed by setup_inputs)
#define BB      2048   // batch
#define NPATCH  196    // patches
#define DD      1024   // dino dim
#define DC      512    // clip dim

// Scratch (allocation-free rule: __device__ globals)
__device__ float g_t[(size_t)BB * DD];          // projected+tanh+normalized text emb
__device__ float g_vsel[(size_t)BB * DD];       // selected+normalized visual emb
__device__ float g_scores[(size_t)BB * NPATCH]; // per-(b,j) cosine scores

// ---------------------------------------------------------------------------
// Packed f32x2 helpers (sm_103a FFMA2 path — only reachable via PTX)
// ---------------------------------------------------------------------------
__device__ __forceinline__ unsigned long long dup2(float x) {
    unsigned long long r;
    unsigned int u = __float_as_uint(x);
    asm("mov.b64 %0, {%1, %1};" : "=l"(r) : "r"(u));
    return r;
}
__device__ __forceinline__ void fma2(unsigned long long& d,
                                     unsigned long long a,
                                     unsigned long long b) {
    asm("fma.rn.f32x2 %0, %1, %2, %0;" : "+l"(d) : "l"(a), "l"(b));
}
__device__ __forceinline__ void unpack2(unsigned long long v, float& lo, float& hi) {
    unsigned int l, h;
    asm("mov.b64 {%0, %1}, %2;" : "=r"(l), "=r"(h) : "l"(v));
    lo = __uint_as_float(l); hi = __uint_as_float(h);
}

// ---------------------------------------------------------------------------
// GEMM: C[M,N] = A[M,K] * B[N,K]^T   (both row-major, K-major contraction)
// BM=BN=128, BK=16, 256 threads, 8x8 per-thread microtile with f32x2 accum.
// Optional epilogue: C = tanh(C + bias[n])
// ---------------------------------------------------------------------------
template <bool TANH>
__global__ __launch_bounds__(256, 2)
void gemm_abt(const float* __restrict__ A, const float* __restrict__ Bm,
              const float* __restrict__ bias, float* __restrict__ C, int K)
{
    __shared__ float As[16][128];
    __shared__ float Bs[16][128];

    const int tid = threadIdx.x;
    const int bm  = blockIdx.y * 128;
    const int bn  = blockIdx.x * 128;
    const int N   = gridDim.x * 128;
    const int tx  = tid & 15;   // 0..15  -> 8 cols each
    const int ty  = tid >> 4;   // 0..15  -> 8 rows each

    // gmem tile load mapping: each thread loads 2 rows (lr, lr+64), 1 float4 each
    const int lr = tid >> 2;          // 0..63
    const int lc = (tid & 3) * 4;     // 0,4,8,12

    // acc2[i][j2] holds C columns (tx*8 + 2*j2, tx*8 + 2*j2 + 1) for row ty*8+i
    unsigned long long acc2[8][4];
#pragma unroll
    for (int i = 0; i < 8; i++)
#pragma unroll
        for (int j = 0; j < 4; j++) acc2[i][j] = 0ULL;

    const float* Aptr = A + (size_t)bm * K;
    const float* Bptr = Bm + (size_t)bn * K;

    for (int k0 = 0; k0 < K; k0 += 16) {
#pragma unroll
        for (int h = 0; h < 2; h++) {
            const int row = lr + h * 64;
            float4 a = *(const float4*)(Aptr + (size_t)row * K + k0 + lc);
            As[lc + 0][row] = a.x; As[lc + 1][row] = a.y;
            As[lc + 2][row] = a.z; As[lc + 3][row] = a.w;
            float4 b = *(const float4*)(Bptr + (size_t)row * K + k0 + lc);
            Bs[lc + 0][row] = b.x; Bs[lc + 1][row] = b.y;
            Bs[lc + 2][row] = b.z; Bs[lc + 3][row] = b.w;
        }
        __syncthreads();

#pragma unroll
        for (int k = 0; k < 16; k++) {
            float af[8];
            *(float4*)&af[0] = *(const float4*)&As[k][ty * 8];
            *(float4*)&af[4] = *(const float4*)&As[k][ty * 8 + 4];
            // B fragment directly as 4 packed f32x2 (pairs of adjacent columns)
            unsigned long long bf2[4];
            ulonglong2 b01 = *(const ulonglong2*)&Bs[k][tx * 8];
            ulonglong2 b23 = *(const ulonglong2*)&Bs[k][tx * 8 + 4];
            bf2[0] = b01.x; bf2[1] = b01.y; bf2[2] = b23.x; bf2[3] = b23.y;

            unsigned long long aa[8];
#pragma unroll
            for (int i = 0; i < 8; i++) aa[i] = dup2(af[i]);
#pragma unroll
            for (int i = 0; i < 8; i++)
#pragma unroll
                for (int j = 0; j < 4; j++)
                    fma2(acc2[i][j], aa[i], bf2[j]);
        }
        __syncthreads();
    }

    // Epilogue
#pragma unroll
    for (int i = 0; i < 8; i++) {
        float* Crow = C + (size_t)(bm + ty * 8 + i) * N + bn + tx * 8;
        float v[8];
#pragma unroll
        for (int j = 0; j < 4; j++) unpack2(acc2[i][j], v[2 * j], v[2 * j + 1]);
        if (TANH) {
#pragma unroll
            for (int j = 0; j < 8; j++) v[j] = tanhf(v[j] + bias[bn + tx * 8 + j]);
        }
        *(float4*)(Crow + 0) = make_float4(v[0], v[1], v[2], v[3]);
        *(float4*)(Crow + 4) = make_float4(v[4], v[5], v[6], v[7]);
    }
}

// ---------------------------------------------------------------------------
// In-place row L2 normalization of X[rows, DD].  One block per row.
// ---------------------------------------------------------------------------
__global__ __launch_bounds__(256)
void normalize_rows(float* __restrict__ X)
{
    const int row = blockIdx.x;
    const int tid = threadIdx.x;
    float4* p = (float4*)(X + (size_t)row * DD);
    float4 a = p[tid];
    float s = a.x * a.x + a.y * a.y + a.z * a.z + a.w * a.w;
#pragma unroll
    for (int o = 16; o; o >>= 1) s += __shfl_xor_sync(0xffffffffu, s, o);

    __shared__ float red[8];
    if ((tid & 31) == 0) red[tid >> 5] = s;
    __syncthreads();
    float tot = red[0] + red[1] + red[2] + red[3] +
                red[4] + red[5] + red[6] + red[7];
    float scale = rsqrtf(fmaxf(tot, 1e-24f));
    a.x *= scale; a.y *= scale; a.z *= scale; a.w *= scale;
    p[tid] = a;
}

// ---------------------------------------------------------------------------
// Pass 1 of max-score alignment: one WARP per (b, j).
// score[b,j] = dot(t_b, v_bj) * rsqrt(||v_bj||^2)   (cosine; t_b already unit)
// Fully parallel: 401K warps, 16 LDG.128 in flight each -> HBM roofline.
// ---------------------------------------------------------------------------
__global__ __launch_bounds__(256)
void scores_kernel(const float* __restrict__ V)
{
    const int gw   = (blockIdx.x * 256 + threadIdx.x) >> 5;
    const int lane = threadIdx.x & 31;
    if (gw >= BB * NPATCH) return;
    const int b = gw / NPATCH;
    const int j = gw - b * NPATCH;

    const float4* v = (const float4*)(V + ((size_t)b * NPATCH + j) * DD);
    const float4* t = (const float4*)(g_t + (size_t)b * DD);

    float d = 0.f, n = 0.f;
#pragma unroll
    for (int s = 0; s < 8; s++) {
        float4 a = v[lane + 32 * s];
        float4 c = t[lane + 32 * s];
        d += a.x * c.x + a.y * c.y + a.z * c.z + a.w * c.w;
        n += a.x * a.x + a.y * a.y + a.z * a.z + a.w * a.w;
    }
#pragma unroll
    for (int o = 16; o; o >>= 1) {
        d += __shfl_xor_sync(0xffffffffu, d, o);
        n += __shfl_xor_sync(0xffffffffu, n, o);
    }
    if (lane == 0)
        g_scores[gw] = d * rsqrtf(fmaxf(n, 1e-24f));
}

// ---------------------------------------------------------------------------
// Pass 2: per batch element, argmax over 196 scores (first-max tie-break,
// matching jnp.argmax), then gather + L2-normalize the selected v row.
// One block (256 threads) per b.
// ---------------------------------------------------------------------------
__global__ __launch_bounds__(256)
void select_kernel(const float* __restrict__ V)
{
    const int b   = blockIdx.x;
    const int tid = threadIdx.x;

    // --- argmax over scores[b, 0..195], prefer lowest index on ties ---
    float best = -3.402823e38f;
    int   bj   = NPATCH;  // sentinel larger than any valid index
    const float* sc = g_scores + (size_t)b * NPATCH;
    for (int j = tid; j < NPATCH; j += 256) {
        float s = sc[j];
        if (s > best || (s == best && j < bj)) { best = s; bj = j; }
    }
    // warp reduce (value desc, index asc)
#pragma unroll
    for (int o = 16; o; o >>= 1) {
        float ob = __shfl_xor_sync(0xffffffffu, best, o);
        int   oj = __shfl_xor_sync(0xffffffffu, bj, o);
        if (ob > best || (ob == best && oj < bj)) { best = ob; bj = oj; }
    }
    __shared__ float rb[8];
    __shared__ int   rj[8];
    if ((tid & 31) == 0) { rb[tid >> 5] = best; rj[tid >> 5] = bj; }
    __syncthreads();
    best = rb[0]; bj = rj[0];
#pragma unroll
    for (int w = 1; w < 8; w++) {
        float ob = rb[w]; int oj = rj[w];
        if (ob > best || (ob == best && oj < bj)) { best = ob; bj = oj; }
    }

    // --- gather + normalize selected row ---
    const float4* v = (const float4*)(V + ((size_t)b * NPATCH + bj) * DD);
    float4 a = v[tid];
    float s = a.x * a.x + a.y * a.y + a.z * a.z + a.w * a.w;
#pragma unroll
    for (int o = 16; o; o >>= 1) s += __shfl_xor_sync(0xffffffffu, s, o);
    __shared__ float rn[8];
    if ((tid & 31) == 0) rn[tid >> 5] = s;
    __syncthreads();
    float tot = rn[0] + rn[1] + rn[2] + rn[3] + rn[4] + rn[5] + rn[6] + rn[7];
    float scale = rsqrtf(fmaxf(tot, 1e-24f));
    a.x *= scale; a.y *= scale; a.z *= scale; a.w *= scale;
    ((float4*)(g_vsel + (size_t)b * DD))[tid] = a;
}

// ---------------------------------------------------------------------------
// Launch: inputs in metadata order:
//   d_in[0] visual_embedding [2048,196,1024] f32
//   d_in[1] textual_embedding [2048,512]     f32
//   d_in[2] W                 [1024,512]     f32
//   d_in[3] b                 [1024]         f32
// d_out: [2048,2048] f32
// ---------------------------------------------------------------------------
extern "C" void kernel_launch(void* const* d_in, const int* in_sizes, int n_in,
                              void* d_out, int out_size)
{
    const float* visual  = (const float*)d_in[0];
    const float* textual = (const float*)d_in[1];
    const float* W       = (const float*)d_in[2];
    const float* bias    = (const float*)d_in[3];
    float* out = (float*)d_out;

    float *t_ptr = nullptr, *vsel_ptr = nullptr;
    cudaGetSymbolAddress((void**)&t_ptr, g_t);
    cudaGetSymbolAddress((void**)&vsel_ptr, g_vsel);

    // 1) t_raw = tanh(textual @ W^T + b)   [2048,1024]
    gemm_abt<true><<<dim3(DD / 128, BB / 128), 256>>>(textual, W, bias, t_ptr, DC);
    // 2) t = l2norm(t_raw)
    normalize_rows<<<BB, 256>>>(t_ptr);
    // 3) scores for all (b,j): one warp per patch row (HBM-bound streaming)
    {
        const int nwarps  = BB * NPATCH;
        const int nblocks = (nwarps * 32 + 255) / 256;
        scores_kernel<<<nblocks, 256>>>(visual);
    }
    // 4) per-b argmax + gather + normalize
    select_kernel<<<BB, 256>>>(visual);
    // 5) out = t @ v_sel^T   [2048,2048]
    gemm_abt<false><<<dim3(BB / 128, BB / 128), 256>>>(t_ptr, vsel_ptr, nullptr, out, DD);
}

// round 3
// speedup vs baseline: 1.1720x; 1.0040x over previous
#include <cuda_runtime.h>

// Problem constants (fixed by setup_inputs)
#define BB      2048   // batch
#define NPATCH  196    // patches
#define DD      1024   // dino dim
#define DC      512    // clip dim

// Scratch (allocation-free rule: __device__ globals)
__device__ float g_t[(size_t)BB * DD];          // projected+tanh+normalized text emb
__device__ float g_vsel[(size_t)BB * DD];       // selected+normalized visual emb
__device__ float g_scores[(size_t)BB * NPATCH]; // per-(b,j) cosine scores

// ---------------------------------------------------------------------------
// Packed f32x2 helpers (sm_103a FFMA2 path — only reachable via PTX)
// ---------------------------------------------------------------------------
__device__ __forceinline__ unsigned long long dup2(float x) {
    unsigned long long r;
    unsigned int u = __float_as_uint(x);
    asm("mov.b64 %0, {%1, %1};" : "=l"(r) : "r"(u));
    return r;
}
__device__ __forceinline__ void fma2(unsigned long long& d,
                                     unsigned long long a,
                                     unsigned long long b) {
    asm("fma.rn.f32x2 %0, %1, %2, %0;" : "+l"(d) : "l"(a), "l"(b));
}
__device__ __forceinline__ void unpack2(unsigned long long v, float& lo, float& hi) {
    unsigned int l, h;
    asm("mov.b64 {%0, %1}, %2;" : "=r"(l), "=r"(h) : "l"(v));
    lo = __uint_as_float(l); hi = __uint_as_float(h);
}

// ---------------------------------------------------------------------------
// GEMM: C[M,N] = A[M,K] * B[N,K]^T   (both row-major, K-major contraction)
// BM=BN=128, BK=16, 256 threads, 8x8 per-thread microtile with f32x2 accum.
// Optional epilogue: C = tanh(C + bias[n])
// ---------------------------------------------------------------------------
template <bool TANH>
__global__ __launch_bounds__(256, 2)
void gemm_abt(const float* __restrict__ A, const float* __restrict__ Bm,
              const float* __restrict__ bias, float* __restrict__ C, int K)
{
    __shared__ float As[16][128];
    __shared__ float Bs[16][128];

    const int tid = threadIdx.x;
    const int bm  = blockIdx.y * 128;
    const int bn  = blockIdx.x * 128;
    const int N   = gridDim.x * 128;
    const int tx  = tid & 15;   // 0..15  -> 8 cols each
    const int ty  = tid >> 4;   // 0..15  -> 8 rows each

    // gmem tile load mapping: each thread loads 2 rows (lr, lr+64), 1 float4 each
    const int lr = tid >> 2;          // 0..63
    const int lc = (tid & 3) * 4;     // 0,4,8,12

    // acc2[i][j2] holds C columns (tx*8 + 2*j2, tx*8 + 2*j2 + 1) for row ty*8+i
    unsigned long long acc2[8][4];
#pragma unroll
    for (int i = 0; i < 8; i++)
#pragma unroll
        for (int j = 0; j < 4; j++) acc2[i][j] = 0ULL;

    const float* Aptr = A + (size_t)bm * K;
    const float* Bptr = Bm + (size_t)bn * K;

    for (int k0 = 0; k0 < K; k0 += 16) {
#pragma unroll
        for (int h = 0; h < 2; h++) {
            const int row = lr + h * 64;
            float4 a = *(const float4*)(Aptr + (size_t)row * K + k0 + lc);
            As[lc + 0][row] = a.x; As[lc + 1][row] = a.y;
            As[lc + 2][row] = a.z; As[lc + 3][row] = a.w;
            float4 b = *(const float4*)(Bptr + (size_t)row * K + k0 + lc);
            Bs[lc + 0][row] = b.x; Bs[lc + 1][row] = b.y;
            Bs[lc + 2][row] = b.z; Bs[lc + 3][row] = b.w;
        }
        __syncthreads();

#pragma unroll
        for (int k = 0; k < 16; k++) {
            float af[8];
            *(float4*)&af[0] = *(const float4*)&As[k][ty * 8];
            *(float4*)&af[4] = *(const float4*)&As[k][ty * 8 + 4];
            // B fragment directly as 4 packed f32x2 (pairs of adjacent columns)
            unsigned long long bf2[4];
            ulonglong2 b01 = *(const ulonglong2*)&Bs[k][tx * 8];
            ulonglong2 b23 = *(const ulonglong2*)&Bs[k][tx * 8 + 4];
            bf2[0] = b01.x; bf2[1] = b01.y; bf2[2] = b23.x; bf2[3] = b23.y;

            unsigned long long aa[8];
#pragma unroll
            for (int i = 0; i < 8; i++) aa[i] = dup2(af[i]);
#pragma unroll
            for (int i = 0; i < 8; i++)
#pragma unroll
                for (int j = 0; j < 4; j++)
                    fma2(acc2[i][j], aa[i], bf2[j]);
        }
        __syncthreads();
    }

    // Epilogue
#pragma unroll
    for (int i = 0; i < 8; i++) {
        float* Crow = C + (size_t)(bm + ty * 8 + i) * N + bn + tx * 8;
        float v[8];
#pragma unroll
        for (int j = 0; j < 4; j++) unpack2(acc2[i][j], v[2 * j], v[2 * j + 1]);
        if (TANH) {
#pragma unroll
            for (int j = 0; j < 8; j++) v[j] = tanhf(v[j] + bias[bn + tx * 8 + j]);
        }
        *(float4*)(Crow + 0) = make_float4(v[0], v[1], v[2], v[3]);
        *(float4*)(Crow + 4) = make_float4(v[4], v[5], v[6], v[7]);
    }
}

// ---------------------------------------------------------------------------
// In-place row L2 normalization of X[rows, DD].  One block per row.
// ---------------------------------------------------------------------------
__global__ __launch_bounds__(256)
void normalize_rows(float* __restrict__ X)
{
    const int row = blockIdx.x;
    const int tid = threadIdx.x;
    float4* p = (float4*)(X + (size_t)row * DD);
    float4 a = p[tid];
    float s = a.x * a.x + a.y * a.y + a.z * a.z + a.w * a.w;
#pragma unroll
    for (int o = 16; o; o >>= 1) s += __shfl_xor_sync(0xffffffffu, s, o);

    __shared__ float red[8];
    if ((tid & 31) == 0) red[tid >> 5] = s;
    __syncthreads();
    float tot = red[0] + red[1] + red[2] + red[3] +
                red[4] + red[5] + red[6] + red[7];
    float scale = rsqrtf(fmaxf(tot, 1e-24f));
    a.x *= scale; a.y *= scale; a.z *= scale; a.w *= scale;
    p[tid] = a;
}

// ---------------------------------------------------------------------------
// Pass 1 of max-score alignment: one WARP per (b, j).
// score[b,j] = dot(t_b, v_bj) * rsqrt(||v_bj||^2)   (cosine; t_b already unit)
// Fully parallel: 401K warps, 16 LDG.128 in flight each -> HBM roofline.
// ---------------------------------------------------------------------------
__global__ __launch_bounds__(256)
void scores_kernel(const float* __restrict__ V)
{
    const int gw   = (blockIdx.x * 256 + threadIdx.x) >> 5;
    const int lane = threadIdx.x & 31;
    if (gw >= BB * NPATCH) return;
    const int b = gw / NPATCH;
    const int j = gw - b * NPATCH;

    const float4* v = (const float4*)(V + ((size_t)b * NPATCH + j) * DD);
    const float4* t = (const float4*)(g_t + (size_t)b * DD);

    float d = 0.f, n = 0.f;
#pragma unroll
    for (int s = 0; s < 8; s++) {
        float4 a = v[lane + 32 * s];
        float4 c = t[lane + 32 * s];
        d += a.x * c.x + a.y * c.y + a.z * c.z + a.w * c.w;
        n += a.x * a.x + a.y * a.y + a.z * a.z + a.w * a.w;
    }
#pragma unroll
    for (int o = 16; o; o >>= 1) {
        d += __shfl_xor_sync(0xffffffffu, d, o);
        n += __shfl_xor_sync(0xffffffffu, n, o);
    }
    if (lane == 0)
        g_scores[gw] = d * rsqrtf(fmaxf(n, 1e-24f));
}

// ---------------------------------------------------------------------------
// Pass 2: per batch element, argmax over 196 scores (first-max tie-break,
// matching jnp.argmax), then gather + L2-normalize the selected v row.
// One block (256 threads) per b.
// ---------------------------------------------------------------------------
__global__ __launch_bounds__(256)
void select_kernel(const float* __restrict__ V)
{
    const int b   = blockIdx.x;
    const int tid = threadIdx.x;

    // --- argmax over scores[b, 0..195], prefer lowest index on ties ---
    float best = -3.402823e38f;
    int   bj   = NPATCH;  // sentinel larger than any valid index
    const float* sc = g_scores + (size_t)b * NPATCH;
    for (int j = tid; j < NPATCH; j += 256) {
        float s = sc[j];
        if (s > best || (s == best && j < bj)) { best = s; bj = j; }
    }
    // warp reduce (value desc, index asc)
#pragma unroll
    for (int o = 16; o; o >>= 1) {
        float ob = __shfl_xor_sync(0xffffffffu, best, o);
        int   oj = __shfl_xor_sync(0xffffffffu, bj, o);
        if (ob > best || (ob == best && oj < bj)) { best = ob; bj = oj; }
    }
    __shared__ float rb[8];
    __shared__ int   rj[8];
    if ((tid & 31) == 0) { rb[tid >> 5] = best; rj[tid >> 5] = bj; }
    __syncthreads();
    best = rb[0]; bj = rj[0];
#pragma unroll
    for (int w = 1; w < 8; w++) {
        float ob = rb[w]; int oj = rj[w];
        if (ob > best || (ob == best && oj < bj)) { best = ob; bj = oj; }
    }

    // --- gather + normalize selected row ---
    const float4* v = (const float4*)(V + ((size_t)b * NPATCH + bj) * DD);
    float4 a = v[tid];
    float s = a.x * a.x + a.y * a.y + a.z * a.z + a.w * a.w;
#pragma unroll
    for (int o = 16; o; o >>= 1) s += __shfl_xor_sync(0xffffffffu, s, o);
    __shared__ float rn[8];
    if ((tid & 31) == 0) rn[tid >> 5] = s;
    __syncthreads();
    float tot = rn[0] + rn[1] + rn[2] + rn[3] + rn[4] + rn[5] + rn[6] + rn[7];
    float scale = rsqrtf(fmaxf(tot, 1e-24f));
    a.x *= scale; a.y *= scale; a.z *= scale; a.w *= scale;
    ((float4*)(g_vsel + (size_t)b * DD))[tid] = a;
}

// ---------------------------------------------------------------------------
// Launch: inputs in metadata order:
//   d_in[0] visual_embedding [2048,196,1024] f32
//   d_in[1] textual_embedding [2048,512]     f32
//   d_in[2] W                 [1024,512]     f32
//   d_in[3] b                 [1024]         f32
// d_out: [2048,2048] f32
// ---------------------------------------------------------------------------
extern "C" void kernel_launch(void* const* d_in, const int* in_sizes, int n_in,
                              void* d_out, int out_size)
{
    const float* visual  = (const float*)d_in[0];
    const float* textual = (const float*)d_in[1];
    const float* W       = (const float*)d_in[2];
    const float* bias    = (const float*)d_in[3];
    float* out = (float*)d_out;

    float *t_ptr = nullptr, *vsel_ptr = nullptr;
    cudaGetSymbolAddress((void**)&t_ptr, g_t);
    cudaGetSymbolAddress((void**)&vsel_ptr, g_vsel);

    // 1) t_raw = tanh(textual @ W^T + b)   [2048,1024]
    gemm_abt<true><<<dim3(DD / 128, BB / 128), 256>>>(textual, W, bias, t_ptr, DC);
    // 2) t = l2norm(t_raw)
    normalize_rows<<<BB, 256>>>(t_ptr);
    // 3) scores for all (b,j): one warp per patch row (HBM-bound streaming)
    {
        const int nwarps  = BB * NPATCH;
        const int nblocks = (nwarps * 32 + 255) / 256;
        scores_kernel<<<nblocks, 256>>>(visual);
    }
    // 4) per-b argmax + gather + normalize
    select_kernel<<<BB, 256>>>(visual);
    // 5) out = t @ v_sel^T   [2048,2048]
    gemm_abt<false><<<dim3(BB / 128, BB / 128), 256>>>(t_ptr, vsel_ptr, nullptr, out, DD);
}